// round 1
// baseline (speedup 1.0000x reference)
#include <cuda_runtime.h>

// StyleGAN 3D x2 upsample, separable [1,4,6,4,1]/16 * 2 per axis.
// Per axis: out[2m]   = 0.5*(x[m-1] + x[m])
//           out[2m+1] = 0.125*x[m-1] + 0.75*x[m] + 0.125*x[m+1]
// Fully fused 3D: each thread maps one input voxel -> 2x2x2 output block.

#define DIN  48
#define DOUT 96
#define TD   4
#define TH   4
#define SD   6   // TD + 2 halo
#define SH   6   // TH + 2 halo
#define SW   50  // 48 + 2 halo

__global__ __launch_bounds__(384)
void upsample3d_kernel(const float* __restrict__ in, float* __restrict__ out)
{
    __shared__ float s[SD][SH][SW];

    const int tx = threadIdx.x;   // 0..47  (input w)
    const int ty = threadIdx.y;   // 0..3   (input h within tile)
    const int tz = threadIdx.z;   // 0..1   (d split)
    const int h0 = blockIdx.x * TH;
    const int d0 = blockIdx.y * TD;
    const int nc = blockIdx.z;    // fused N*C (4*32 = 128)

    const float* __restrict__ src = in  + (size_t)nc * (DIN * DIN * DIN);
    float*       __restrict__ dst = out + (size_t)nc * (DOUT * DOUT * DOUT);

    // ---- cooperative smem load with halo (zero-pad OOB) ----
    const int tid = (tz * 4 + ty) * 48 + tx;   // 0..383
    for (int i = tid; i < SD * SH * SW; i += 384) {
        int w = i % SW - 1;
        int r = i / SW;
        int h = r % SH - 1 + h0;
        int d = r / SH - 1 + d0;
        float v = 0.0f;
        if ((unsigned)w < DIN && (unsigned)h < DIN && (unsigned)d < DIN)
            v = src[((size_t)d * DIN + h) * DIN + w];
        ((float*)s)[i] = v;
    }
    __syncthreads();

    // ---- compute: each thread does 2 input-d rows -> 16 outputs ----
    #pragma unroll
    for (int dd = 0; dd < 2; dd++) {
        const int ld = tz * 2 + dd;           // local input d in 0..3

        // W pass: 3x3 (d,h) neighborhood -> even/odd along w
        float wE[3][3], wO[3][3];
        #pragma unroll
        for (int i = 0; i < 3; i++) {
            #pragma unroll
            for (int j = 0; j < 3; j++) {
                float xm = s[ld + i][ty + j][tx];
                float x0 = s[ld + i][ty + j][tx + 1];
                float xp = s[ld + i][ty + j][tx + 2];
                wE[i][j] = 0.5f * (xm + x0);
                wO[i][j] = 0.75f * x0 + 0.125f * (xm + xp);
            }
        }

        // H pass: hv[hs][ws][i]  (hs,ws = even/odd selectors, i = d index)
        float hv[2][2][3];
        #pragma unroll
        for (int i = 0; i < 3; i++) {
            hv[0][0][i] = 0.5f * (wE[i][0] + wE[i][1]);
            hv[1][0][i] = 0.75f * wE[i][1] + 0.125f * (wE[i][0] + wE[i][2]);
            hv[0][1][i] = 0.5f * (wO[i][0] + wO[i][1]);
            hv[1][1][i] = 0.75f * wO[i][1] + 0.125f * (wO[i][0] + wO[i][2]);
        }

        // D pass -> r[dz][hs][ws]
        float r[2][2][2];
        #pragma unroll
        for (int hs = 0; hs < 2; hs++) {
            #pragma unroll
            for (int ws = 0; ws < 2; ws++) {
                float v0 = hv[hs][ws][0], v1 = hv[hs][ws][1], v2 = hv[hs][ws][2];
                r[0][hs][ws] = 0.5f * (v0 + v1);
                r[1][hs][ws] = 0.75f * v1 + 0.125f * (v0 + v2);
            }
        }

        // ---- coalesced float2 stores (w pair is contiguous) ----
        const int od = 2 * (d0 + ld);
        const int oh = 2 * (h0 + ty);
        const int ow = 2 * tx;
        #pragma unroll
        for (int dz = 0; dz < 2; dz++) {
            #pragma unroll
            for (int hs = 0; hs < 2; hs++) {
                float2 v = make_float2(r[dz][hs][0], r[dz][hs][1]);
                *(float2*)&dst[((size_t)(od + dz) * DOUT + (oh + hs)) * DOUT + ow] = v;
            }
        }
    }
}

extern "C" void kernel_launch(void* const* d_in, const int* in_sizes, int n_in,
                              void* d_out, int out_size)
{
    const float* x = (const float*)d_in[0];
    float* y = (float*)d_out;
    dim3 block(48, 4, 2);                 // 384 threads
    dim3 grid(DIN / TH, DIN / TD, 128);   // 12 x 12 x (N*C)
    upsample3d_kernel<<<grid, block>>>(x, y);
}

// round 3
// speedup vs baseline: 1.3479x; 1.3479x over previous
#include <cuda_runtime.h>

// StyleGAN 3D x2 upsample, separable [1,4,6,4,1]/16 * 2 per axis.
// Per axis: out[2m]   = 0.5*(x[m-1] + x[m])
//           out[2m+1] = 0.125*x[m-1] + 0.75*x[m] + 0.125*x[m+1]
//
// Each thread: 2(w) x 1(h) x 2(d) input voxels -> 4x2x4 output block (32 floats).
// W+H pass fused and computed ONCE for the 4 d-window rows, D pass applied twice.
// All gmem traffic is 128-bit (float4); w-halo is identically zero.

#define DIN   48
#define DOUT  96
#define TD    8      // input-d per block
#define TH    4      // input-h per block
#define SD    10     // TD + 2 halo
#define SHH   6      // TH + 2 halo
#define SW    56     // data at [4..51], halo zeros at [3] and [52]

__global__ __launch_bounds__(384)
void upsample3d_kernel(const float* __restrict__ in, float* __restrict__ out)
{
    __shared__ float s[SD][SHH][SW];

    const int tx = threadIdx.x;            // 0..23  (w pair: input w = 2tx, 2tx+1)
    const int ty = threadIdx.y;            // 0..3   (input h in tile)
    const int tz = threadIdx.z;            // 0..3   (input d pair in tile)
    const int h0 = blockIdx.x * TH;
    const int d0 = blockIdx.y * TD;
    const int nc = blockIdx.z;             // fused N*C = 128

    const float* __restrict__ src = in  + (size_t)nc * (DIN * DIN * DIN);
    float*       __restrict__ dst = out + (size_t)nc * (DOUT * DOUT * DOUT);

    const int tid = (tz * 4 + ty) * 24 + tx;   // 0..383

    // ---- fill: 60 (d,h) rows x 12 float4 chunks = 720 LDG.128 ----
    #pragma unroll
    for (int it = 0; it < 2; it++) {
        int i = tid + it * 384;
        if (i < (SD * SHH) * 12) {
            int r = i / 12, c = i % 12;          // const-div -> cheap
            int h = r % SHH - 1 + h0;
            int d = r / SHH - 1 + d0;
            float4 v = make_float4(0.f, 0.f, 0.f, 0.f);
            if ((unsigned)h < DIN && (unsigned)d < DIN)
                v = *(const float4*)&src[((size_t)d * DIN + h) * DIN + 4 * c];
            *(float4*)&s[r / SHH][r % SHH][4 + 4 * c] = v;
        }
    }
    // ---- w-halo columns are always out-of-range -> zero ----
    if (tid < SD * SHH * 2) {
        int r = tid >> 1;
        s[r / SHH][r % SHH][(tid & 1) ? 52 : 3] = 0.f;
    }
    __syncthreads();

    // ---- fused W+H pass, once per d-window row (4 rows) ----
    // hv[i][k]: i = d-window row (input d = d0 + 2tz + i - 1)
    //           k = 0..3 even-h {E0,O0,E1,O1}, 4..7 odd-h {E0,O0,E1,O1}
    const int wb = 3 + 2 * tx;   // index of x[w0-1] in s row
    float hv[4][8];
    #pragma unroll
    for (int i = 0; i < 4; i++) {
        const int rd = 2 * tz + i;
        float e0[3], o0[3], e1[3], o1[3];
        #pragma unroll
        for (int j = 0; j < 3; j++) {
            const float* p = &s[rd][ty + j][wb];
            float a = p[0], b = p[1], c = p[2], d = p[3];
            e0[j] = 0.5f * (a + b);
            o0[j] = 0.75f * b + 0.125f * (a + c);
            e1[j] = 0.5f * (b + c);
            o1[j] = 0.75f * c + 0.125f * (b + d);
        }
        hv[i][0] = 0.5f * (e0[0] + e0[1]);
        hv[i][1] = 0.5f * (o0[0] + o0[1]);
        hv[i][2] = 0.5f * (e1[0] + e1[1]);
        hv[i][3] = 0.5f * (o1[0] + o1[1]);
        hv[i][4] = 0.75f * e0[1] + 0.125f * (e0[0] + e0[2]);
        hv[i][5] = 0.75f * o0[1] + 0.125f * (o0[0] + o0[2]);
        hv[i][6] = 0.75f * e1[1] + 0.125f * (e1[0] + e1[2]);
        hv[i][7] = 0.75f * o1[1] + 0.125f * (o1[0] + o1[2]);
    }

    // ---- D pass + float4 stores ----
    const int oh = 2 * (h0 + ty);
    const int ow = 4 * tx;
    #pragma unroll
    for (int dd = 0; dd < 2; dd++) {
        const int od = 2 * (d0 + 2 * tz + dd);
        const float* A = hv[dd];
        const float* B = hv[dd + 1];
        const float* C = hv[dd + 2];
        #pragma unroll
        for (int hs = 0; hs < 2; hs++) {
            const int o = hs * 4;
            float4 vE, vO;
            vE.x = 0.5f * (A[o + 0] + B[o + 0]);
            vE.y = 0.5f * (A[o + 1] + B[o + 1]);
            vE.z = 0.5f * (A[o + 2] + B[o + 2]);
            vE.w = 0.5f * (A[o + 3] + B[o + 3]);
            vO.x = 0.75f * B[o + 0] + 0.125f * (A[o + 0] + C[o + 0]);
            vO.y = 0.75f * B[o + 1] + 0.125f * (A[o + 1] + C[o + 1]);
            vO.z = 0.75f * B[o + 2] + 0.125f * (A[o + 2] + C[o + 2]);
            vO.w = 0.75f * B[o + 3] + 0.125f * (A[o + 3] + C[o + 3]);
            *(float4*)&dst[((size_t)od * DOUT + (oh + hs)) * DOUT + ow] = vE;
            *(float4*)&dst[((size_t)(od + 1) * DOUT + (oh + hs)) * DOUT + ow] = vO;
        }
    }
}

extern "C" void kernel_launch(void* const* d_in, const int* in_sizes, int n_in,
                              void* d_out, int out_size)
{
    const float* x = (const float*)d_in[0];
    float* y = (float*)d_out;
    dim3 block(24, 4, 4);                        // 384 threads
    dim3 grid(DIN / TH, DIN / TD, 128);          // 12 x 6 x (N*C)
    upsample3d_kernel<<<grid, block>>>(x, y);
}

// round 4
// speedup vs baseline: 1.5360x; 1.1395x over previous
#include <cuda_runtime.h>

// StyleGAN 3D x2 upsample, separable [1,4,6,4,1]/16 * 2 per axis.
// Per axis: out[2m]   = 0.5*(x[m-1] + x[m])
//           out[2m+1] = 0.125*x[m-1] + 0.75*x[m] + 0.125*x[m+1]
//
// Two-stage: Stage A computes the W-pass ONCE per element into smem
// (96-wide rows, 16B-aligned quads). Stage B reads aligned LDS.128 and
// applies H then D passes, writing STG.128.

#define DIN   48
#define DOUT  96
#define TD    8            // input-d per block
#define TH    4            // input-h per block
#define SD    10           // TD + 2 halo
#define SHH   6            // TH + 2 halo
#define SW2   104          // 96 W-values + pad

__global__ __launch_bounds__(384)
void upsample3d_kernel(const float* __restrict__ in, float* __restrict__ out)
{
    __shared__ float s2[SD][SHH][SW2];

    const int tx = threadIdx.x;            // 0..23
    const int ty = threadIdx.y;            // 0..3
    const int tz = threadIdx.z;            // 0..3
    const int h0 = blockIdx.x * TH;
    const int d0 = blockIdx.y * TD;
    const int nc = blockIdx.z;             // fused N*C = 128

    const float* __restrict__ src = in  + (size_t)nc * (DIN * DIN * DIN);
    float*       __restrict__ dst = out + (size_t)nc * (DOUT * DOUT * DOUT);

    const int tid = (tz * 4 + ty) * 24 + tx;   // 0..383

    // ================= Stage A: W-pass into smem =================
    // 60 (d,h) rows x 6 w-segments; each thread: 8 inputs -> 16 W-outputs.
    if (tid < 60 * 6) {
        const int seg = tid % 6;           // w segment: inputs [8seg..8seg+7]
        const int r   = tid / 6;           // 0..59
        const int rh  = r % SHH;           // 0..5
        const int rd  = r / SHH;           // 0..9
        const int h   = rh - 1 + h0;
        const int d   = rd - 1 + d0;

        float xin[10];                     // x[m-1] .. x[m+8]
        if ((unsigned)h < DIN && (unsigned)d < DIN) {
            const float* p = src + ((size_t)d * DIN + h) * DIN + 8 * seg;
            float4 a = *(const float4*)p;
            float4 b = *(const float4*)(p + 4);
            xin[0] = (seg > 0) ? p[-1] : 0.f;
            xin[1] = a.x; xin[2] = a.y; xin[3] = a.z; xin[4] = a.w;
            xin[5] = b.x; xin[6] = b.y; xin[7] = b.z; xin[8] = b.w;
            xin[9] = (seg < 5) ? p[8] : 0.f;
        } else {
            #pragma unroll
            for (int k = 0; k < 10; k++) xin[k] = 0.f;
        }

        float w16[16];
        #pragma unroll
        for (int k = 0; k < 8; k++) {
            w16[2 * k]     = 0.5f  * (xin[k] + xin[k + 1]);
            w16[2 * k + 1] = 0.75f * xin[k + 1] + 0.125f * (xin[k] + xin[k + 2]);
        }
        float* srow = &s2[rd][rh][16 * seg];
        #pragma unroll
        for (int q = 0; q < 4; q++)
            *(float4*)&srow[4 * q] = *(float4*)&w16[4 * q];
    }
    __syncthreads();

    // ================= Stage B: H + D passes =================
    // Thread: w-quad 4tx, input-h (h0+ty), input-d pair (d0+2tz, +1)
    // -> output 4(w) x 2(h) x 4(d) = 8 x STG.128.

    // H-pass for the 4 d-window rows -> hv[i][hs] quads
    float4 hv[4][2];
    #pragma unroll
    for (int i = 0; i < 4; i++) {
        const int rd = 2 * tz + i;
        float4 q0 = *(const float4*)&s2[rd][ty + 0][4 * tx];
        float4 q1 = *(const float4*)&s2[rd][ty + 1][4 * tx];
        float4 q2 = *(const float4*)&s2[rd][ty + 2][4 * tx];
        float4 e, o;
        e.x = 0.5f * (q0.x + q1.x);  o.x = 0.75f * q1.x + 0.125f * (q0.x + q2.x);
        e.y = 0.5f * (q0.y + q1.y);  o.y = 0.75f * q1.y + 0.125f * (q0.y + q2.y);
        e.z = 0.5f * (q0.z + q1.z);  o.z = 0.75f * q1.z + 0.125f * (q0.z + q2.z);
        e.w = 0.5f * (q0.w + q1.w);  o.w = 0.75f * q1.w + 0.125f * (q0.w + q2.w);
        hv[i][0] = e;
        hv[i][1] = o;
    }

    const int oh = 2 * (h0 + ty);
    const int ow = 4 * tx;
    #pragma unroll
    for (int dd = 0; dd < 2; dd++) {
        const int od = 2 * (d0 + 2 * tz + dd);
        #pragma unroll
        for (int hs = 0; hs < 2; hs++) {
            float4 A = hv[dd][hs], B = hv[dd + 1][hs], C = hv[dd + 2][hs];
            float4 vE, vO;
            vE.x = 0.5f * (A.x + B.x);  vO.x = 0.75f * B.x + 0.125f * (A.x + C.x);
            vE.y = 0.5f * (A.y + B.y);  vO.y = 0.75f * B.y + 0.125f * (A.y + C.y);
            vE.z = 0.5f * (A.z + B.z);  vO.z = 0.75f * B.z + 0.125f * (A.z + C.z);
            vE.w = 0.5f * (A.w + B.w);  vO.w = 0.75f * B.w + 0.125f * (A.w + C.w);
            *(float4*)&dst[((size_t)od * DOUT + (oh + hs)) * DOUT + ow] = vE;
            *(float4*)&dst[((size_t)(od + 1) * DOUT + (oh + hs)) * DOUT + ow] = vO;
        }
    }
}

extern "C" void kernel_launch(void* const* d_in, const int* in_sizes, int n_in,
                              void* d_out, int out_size)
{
    const float* x = (const float*)d_in[0];
    float* y = (float*)d_out;
    dim3 block(24, 4, 4);                        // 384 threads
    dim3 grid(DIN / TH, DIN / TD, 128);          // 12 x 6 x (N*C)
    upsample3d_kernel<<<grid, block>>>(x, y);
}

// round 5
// speedup vs baseline: 1.6576x; 1.0792x over previous
#include <cuda_runtime.h>

// StyleGAN 3D x2 upsample, separable [1,4,6,4,1]/16 * 2 per axis.
// Per axis: out[2m]   = 0.5*(x[m-1] + x[m])
//           out[2m+1] = 0.125*x[m-1] + 0.75*x[m] + 0.125*x[m+1]
//
// Stage A: W-pass once per element into smem (aligned quads).
// Stage B: per-thread rolling 3-row H ring over ALL 10 d-window rows;
// H computed exactly once per row, D-pass emits STG.128 pairs.

#define DIN   48
#define DOUT  96
#define TD    8            // input-d per block
#define TH    8            // input-h per block
#define SD    10           // TD + 2 halo
#define SHH   10           // TH + 2 halo
#define SW2   104          // 96 W-values + pad

__global__ __launch_bounds__(192)
void upsample3d_kernel(const float* __restrict__ in, float* __restrict__ out)
{
    __shared__ float s2[SD][SHH][SW2];

    const int tx = threadIdx.x;            // 0..23  (W-output quad)
    const int ty = threadIdx.y;            // 0..7   (input h in tile)
    const int h0 = blockIdx.x * TH;
    const int d0 = blockIdx.y * TD;
    const int nc = blockIdx.z;             // fused N*C = 128

    const float* __restrict__ src = in  + (size_t)nc * (DIN * DIN * DIN);
    float*       __restrict__ dst = out + (size_t)nc * (DOUT * DOUT * DOUT);

    const int tid = ty * 24 + tx;          // 0..191

    // ================= Stage A: W-pass into smem =================
    // 100 (d,h) rows x 6 w-segments = 600 tasks.
    for (int i = tid; i < SD * SHH * 6; i += 192) {
        const int seg = i % 6;             // inputs [8seg..8seg+7]
        const int r   = i / 6;             // 0..99
        const int rh  = r % SHH;
        const int rd  = r / SHH;
        const int h   = rh - 1 + h0;
        const int d   = rd - 1 + d0;

        float xin[10];                     // x[m-1] .. x[m+8]
        if ((unsigned)h < DIN && (unsigned)d < DIN) {
            const float* p = src + ((size_t)d * DIN + h) * DIN + 8 * seg;
            float4 a = *(const float4*)p;
            float4 b = *(const float4*)(p + 4);
            xin[0] = (seg > 0) ? p[-1] : 0.f;
            xin[1] = a.x; xin[2] = a.y; xin[3] = a.z; xin[4] = a.w;
            xin[5] = b.x; xin[6] = b.y; xin[7] = b.z; xin[8] = b.w;
            xin[9] = (seg < 5) ? p[8] : 0.f;
        } else {
            #pragma unroll
            for (int k = 0; k < 10; k++) xin[k] = 0.f;
        }

        float w16[16];
        #pragma unroll
        for (int k = 0; k < 8; k++) {
            w16[2 * k]     = 0.5f  * (xin[k] + xin[k + 1]);
            w16[2 * k + 1] = 0.75f * xin[k + 1] + 0.125f * (xin[k] + xin[k + 2]);
        }
        float* srow = &s2[rd][rh][16 * seg];
        #pragma unroll
        for (int q = 0; q < 4; q++)
            *(float4*)&srow[4 * q] = *(float4*)&w16[4 * q];
    }
    __syncthreads();

    // ================= Stage B: H + D with rolling d-window =================
    // Thread: w-quad 4tx, input-h (h0+ty); walks all 10 d-window rows.
    const int oh = 2 * (h0 + ty);
    const int ow = 4 * tx;

    float4 hv[3][2];                       // ring: H result (even-h, odd-h) quads

    #pragma unroll
    for (int i = 0; i < SD; i++) {
        // ---- H-pass for d-window row i (computed once) ----
        {
            float4 q0 = *(const float4*)&s2[i][ty + 0][4 * tx];
            float4 q1 = *(const float4*)&s2[i][ty + 1][4 * tx];
            float4 q2 = *(const float4*)&s2[i][ty + 2][4 * tx];
            float4 e, o;
            e.x = 0.5f * (q0.x + q1.x);  o.x = 0.75f * q1.x + 0.125f * (q0.x + q2.x);
            e.y = 0.5f * (q0.y + q1.y);  o.y = 0.75f * q1.y + 0.125f * (q0.y + q2.y);
            e.z = 0.5f * (q0.z + q1.z);  o.z = 0.75f * q1.z + 0.125f * (q0.z + q2.z);
            e.w = 0.5f * (q0.w + q1.w);  o.w = 0.75f * q1.w + 0.125f * (q0.w + q2.w);
            hv[i % 3][0] = e;
            hv[i % 3][1] = o;
        }

        // ---- D-pass for output pair p = i-2 (needs rows i-2, i-1, i) ----
        if (i >= 2) {
            const int p  = i - 2;                  // 0..7
            const int od = 2 * (d0 + p);
            #pragma unroll
            for (int hs = 0; hs < 2; hs++) {
                float4 A = hv[(i - 2) % 3][hs];
                float4 B = hv[(i - 1) % 3][hs];
                float4 C = hv[i % 3][hs];
                float4 vE, vO;
                vE.x = 0.5f * (A.x + B.x);  vO.x = 0.75f * B.x + 0.125f * (A.x + C.x);
                vE.y = 0.5f * (A.y + B.y);  vO.y = 0.75f * B.y + 0.125f * (A.y + C.y);
                vE.z = 0.5f * (A.z + B.z);  vO.z = 0.75f * B.z + 0.125f * (A.z + C.z);
                vE.w = 0.5f * (A.w + B.w);  vO.w = 0.75f * B.w + 0.125f * (A.w + C.w);
                *(float4*)&dst[((size_t)od * DOUT + (oh + hs)) * DOUT + ow] = vE;
                *(float4*)&dst[((size_t)(od + 1) * DOUT + (oh + hs)) * DOUT + ow] = vO;
            }
        }
    }
}

extern "C" void kernel_launch(void* const* d_in, const int* in_sizes, int n_in,
                              void* d_out, int out_size)
{
    const float* x = (const float*)d_in[0];
    float* y = (float*)d_out;
    dim3 block(24, 8, 1);                        // 192 threads
    dim3 grid(DIN / TH, DIN / TD, 128);          // 6 x 6 x (N*C)
    upsample3d_kernel<<<grid, block>>>(x, y);
}

// round 6
// speedup vs baseline: 1.6967x; 1.0236x over previous
#include <cuda_runtime.h>

// StyleGAN 3D x2 upsample, separable [1,4,6,4,1]/16 * 2 per axis.
// Per axis: out[2m]   = 0.5*(x[m-1] + x[m])
//           out[2m+1] = 0.125*x[m-1] + 0.75*x[m] + 0.125*x[m+1]
//
// Stage A: W-pass once per element into smem (aligned quads).
// Stage B: per-thread rolling 3-row H ring over all SD d-window rows;
// H computed exactly once per row, D-pass emits streaming STG.128 pairs.
// Tile sized for 6 blocks/SM (32KB smem, <=56 regs) and a ~92% final wave.

#define DIN   48
#define DOUT  96
#define TD    6            // input-d per block
#define TH    8            // input-h per block
#define SD    8            // TD + 2 halo
#define SHH   10           // TH + 2 halo
#define SW2   100          // 96 W-values + pad (rows stay 16B-aligned)

__global__ __launch_bounds__(192, 6)
void upsample3d_kernel(const float* __restrict__ in, float* __restrict__ out)
{
    __shared__ float s2[SD][SHH][SW2];

    const int tx = threadIdx.x;            // 0..23  (W-output quad)
    const int ty = threadIdx.y;            // 0..7   (input h in tile)
    const int h0 = blockIdx.x * TH;
    const int d0 = blockIdx.y * TD;
    const int nc = blockIdx.z;             // fused N*C = 128

    const float* __restrict__ src = in  + (size_t)nc * (DIN * DIN * DIN);
    float*       __restrict__ dst = out + (size_t)nc * (DOUT * DOUT * DOUT);

    const int tid = ty * 24 + tx;          // 0..191

    // ================= Stage A: W-pass into smem =================
    // SD*SHH (d,h) rows x 6 w-segments = 480 tasks.
    for (int i = tid; i < SD * SHH * 6; i += 192) {
        const int seg = i % 6;             // inputs [8seg..8seg+7]
        const int r   = i / 6;             // 0..79
        const int rh  = r % SHH;
        const int rd  = r / SHH;
        const int h   = rh - 1 + h0;
        const int d   = rd - 1 + d0;

        float xin[10];                     // x[m-1] .. x[m+8]
        if ((unsigned)h < DIN && (unsigned)d < DIN) {
            const float* p = src + ((size_t)d * DIN + h) * DIN + 8 * seg;
            float4 a = *(const float4*)p;
            float4 b = *(const float4*)(p + 4);
            xin[0] = (seg > 0) ? p[-1] : 0.f;
            xin[1] = a.x; xin[2] = a.y; xin[3] = a.z; xin[4] = a.w;
            xin[5] = b.x; xin[6] = b.y; xin[7] = b.z; xin[8] = b.w;
            xin[9] = (seg < 5) ? p[8] : 0.f;
        } else {
            #pragma unroll
            for (int k = 0; k < 10; k++) xin[k] = 0.f;
        }

        float w16[16];
        #pragma unroll
        for (int k = 0; k < 8; k++) {
            w16[2 * k]     = 0.5f  * (xin[k] + xin[k + 1]);
            w16[2 * k + 1] = 0.75f * xin[k + 1] + 0.125f * (xin[k] + xin[k + 2]);
        }
        float* srow = &s2[rd][rh][16 * seg];
        #pragma unroll
        for (int q = 0; q < 4; q++)
            *(float4*)&srow[4 * q] = *(float4*)&w16[4 * q];
    }
    __syncthreads();

    // ================= Stage B: H + D with rolling d-window =================
    // Thread: w-quad 4tx, input-h (h0+ty); walks all SD d-window rows.
    const int oh = 2 * (h0 + ty);
    const int ow = 4 * tx;

    float4 hv[3][2];                       // ring: H result (even-h, odd-h) quads

    #pragma unroll
    for (int i = 0; i < SD; i++) {
        // ---- H-pass for d-window row i (computed once) ----
        {
            float4 q0 = *(const float4*)&s2[i][ty + 0][4 * tx];
            float4 q1 = *(const float4*)&s2[i][ty + 1][4 * tx];
            float4 q2 = *(const float4*)&s2[i][ty + 2][4 * tx];
            float4 e, o;
            e.x = 0.5f * (q0.x + q1.x);  o.x = 0.75f * q1.x + 0.125f * (q0.x + q2.x);
            e.y = 0.5f * (q0.y + q1.y);  o.y = 0.75f * q1.y + 0.125f * (q0.y + q2.y);
            e.z = 0.5f * (q0.z + q1.z);  o.z = 0.75f * q1.z + 0.125f * (q0.z + q2.z);
            e.w = 0.5f * (q0.w + q1.w);  o.w = 0.75f * q1.w + 0.125f * (q0.w + q2.w);
            hv[i % 3][0] = e;
            hv[i % 3][1] = o;
        }

        // ---- D-pass for output pair p = i-2 (needs rows i-2, i-1, i) ----
        if (i >= 2) {
            const int p  = i - 2;                  // 0..TD-1
            const int od = 2 * (d0 + p);
            #pragma unroll
            for (int hs = 0; hs < 2; hs++) {
                float4 A = hv[(i - 2) % 3][hs];
                float4 B = hv[(i - 1) % 3][hs];
                float4 C = hv[i % 3][hs];
                float4 vE, vO;
                vE.x = 0.5f * (A.x + B.x);  vO.x = 0.75f * B.x + 0.125f * (A.x + C.x);
                vE.y = 0.5f * (A.y + B.y);  vO.y = 0.75f * B.y + 0.125f * (A.y + C.y);
                vE.z = 0.5f * (A.z + B.z);  vO.z = 0.75f * B.z + 0.125f * (A.z + C.z);
                vE.w = 0.5f * (A.w + B.w);  vO.w = 0.75f * B.w + 0.125f * (A.w + C.w);
                __stcs((float4*)&dst[((size_t)od * DOUT + (oh + hs)) * DOUT + ow], vE);
                __stcs((float4*)&dst[((size_t)(od + 1) * DOUT + (oh + hs)) * DOUT + ow], vO);
            }
        }
    }
}

extern "C" void kernel_launch(void* const* d_in, const int* in_sizes, int n_in,
                              void* d_out, int out_size)
{
    const float* x = (const float*)d_in[0];
    float* y = (float*)d_out;
    dim3 block(24, 8, 1);                        // 192 threads
    dim3 grid(DIN / TH, DIN / TD, 128);          // 6 x 8 x (N*C) = 6144 blocks
    upsample3d_kernel<<<grid, block>>>(x, y);
}

// round 7
// speedup vs baseline: 1.7758x; 1.0466x over previous
#include <cuda_runtime.h>

// StyleGAN 3D x2 upsample, separable [1,4,6,4,1]/16 * 2 per axis.
// Per axis: out[2m]   = 0.5*(x[m-1] + x[m])
//           out[2m+1] = 0.125*x[m-1] + 0.75*x[m] + 0.125*x[m+1]
//
// Stage A: raw input tile -> smem (LDG.128 / STS.128, zero-padded halo).
// Stage B: per-thread rolling 3-row ring; W+H fused from raw smem, D-pass
// writes to a double-buffered smem staging tile (STS.128, 4cyc crossbar),
// drained to gmem by cp.async.bulk S->G on the TMA pipe (bypasses the
// 12cyc/instr STG.128 LSU cost that bound the previous version).

#define DIN   48
#define DOUT  96
#define TD    6            // input-d per block
#define TH    8            // input-h per block
#define SD    8            // TD + 2 halo
#define SHH   10           // TH + 2 halo
#define SWR   56           // zeros[0..3], x[4..51], zeros[52..55]

__device__ __forceinline__ unsigned sm32(const void* p) {
    return (unsigned)__cvta_generic_to_shared(p);
}

__global__ __launch_bounds__(192, 5)
void upsample3d_kernel(const float* __restrict__ in, float* __restrict__ out)
{
    __shared__ float s2[SD][SHH][SWR];            // raw input tile (17.5 KB)
    __shared__ float stg[2][2][2 * TH][DOUT];     // staging, 2 bufs x 2 planes (24 KB)

    const int tx = threadIdx.x;            // 0..23  (output w quad = 4tx)
    const int ty = threadIdx.y;            // 0..7   (input h in tile)
    const int h0 = blockIdx.x * TH;
    const int d0 = blockIdx.y * TD;
    const int nc = blockIdx.z;             // fused N*C = 128

    const float* __restrict__ src = in  + (size_t)nc * (DIN * DIN * DIN);
    float*       __restrict__ dst = out + (size_t)nc * ((size_t)DOUT * DOUT * DOUT);

    const int tid = ty * 24 + tx;          // 0..191

    // ================= Stage A: raw fill (960 float4 tasks = 5/thread) =====
    #pragma unroll
    for (int it = 0; it < 5; it++) {
        const int i  = tid + it * 192;     // 0..959
        const int c  = i % 12;
        const int r  = i / 12;
        const int rh = r % SHH;
        const int rd = r / SHH;
        const int h  = rh - 1 + h0;
        const int d  = rd - 1 + d0;
        float4 v = make_float4(0.f, 0.f, 0.f, 0.f);
        if ((unsigned)h < DIN && (unsigned)d < DIN)
            v = *(const float4*)&src[((size_t)d * DIN + h) * DIN + 4 * c];
        *(float4*)&s2[rd][rh][4 + 4 * c] = v;
    }
    if (tid < SD * SHH * 2) {              // w-halo pads
        const int r = tid >> 1;
        *(float4*)&s2[r / SHH][r % SHH][(tid & 1) ? 52 : 0] =
            make_float4(0.f, 0.f, 0.f, 0.f);
    }
    __syncthreads();

    // ================= Stage B: W+H+D rolling ring, bulk-copied out ========
    const int wb = 2 * tx + 3;             // s2 index of x[2tx-1]
    float4 hv[3][2];                       // ring of H results (even-h, odd-h)

    #pragma unroll
    for (int i = 0; i < SD; i++) {
        // ---- W then H for d-window row i (once per row) ----
        float4 w[3];
        #pragma unroll
        for (int j = 0; j < 3; j++) {
            const float* row = s2[i][ty + j];
            float  a  = row[wb];                          // x[2tx-1]
            float2 bc = *(const float2*)&row[wb + 1];     // x[2tx], x[2tx+1]
            float  dd = row[wb + 3];                      // x[2tx+2]
            w[j].x = 0.5f  * (a + bc.x);
            w[j].y = 0.75f * bc.x + 0.125f * (a + bc.y);
            w[j].z = 0.5f  * (bc.x + bc.y);
            w[j].w = 0.75f * bc.y + 0.125f * (bc.x + dd);
        }
        {
            float4 e, o;
            e.x = 0.5f * (w[0].x + w[1].x);  o.x = 0.75f * w[1].x + 0.125f * (w[0].x + w[2].x);
            e.y = 0.5f * (w[0].y + w[1].y);  o.y = 0.75f * w[1].y + 0.125f * (w[0].y + w[2].y);
            e.z = 0.5f * (w[0].z + w[1].z);  o.z = 0.75f * w[1].z + 0.125f * (w[0].z + w[2].z);
            e.w = 0.5f * (w[0].w + w[1].w);  o.w = 0.75f * w[1].w + 0.125f * (w[0].w + w[2].w);
            hv[i % 3][0] = e;
            hv[i % 3][1] = o;
        }

        // ---- D-pass for output pair p = i-2 ----
        if (i >= 2) {
            const int p   = i - 2;         // 0..TD-1 (compile-time after unroll)
            const int buf = p & 1;

            float4 vE[2], vO[2];
            #pragma unroll
            for (int hs = 0; hs < 2; hs++) {
                float4 A = hv[(i - 2) % 3][hs];
                float4 B = hv[(i - 1) % 3][hs];
                float4 C = hv[i % 3][hs];
                vE[hs].x = 0.5f * (A.x + B.x);  vO[hs].x = 0.75f * B.x + 0.125f * (A.x + C.x);
                vE[hs].y = 0.5f * (A.y + B.y);  vO[hs].y = 0.75f * B.y + 0.125f * (A.y + C.y);
                vE[hs].z = 0.5f * (A.z + B.z);  vO[hs].z = 0.75f * B.z + 0.125f * (A.z + C.z);
                vE[hs].w = 0.5f * (A.w + B.w);  vO[hs].w = 0.75f * B.w + 0.125f * (A.w + C.w);
            }

            // buffer (p&1) was consumed by bulk group p-2; wait for its reads
            if (p >= 2 && tid == 0)
                asm volatile("cp.async.bulk.wait_group.read 1;" ::: "memory");
            __syncthreads();

            #pragma unroll
            for (int hs = 0; hs < 2; hs++) {
                *(float4*)&stg[buf][0][2 * ty + hs][4 * tx] = vE[hs];
                *(float4*)&stg[buf][1][2 * ty + hs][4 * tx] = vO[hs];
            }
            __syncthreads();

            if (tid == 0) {
                asm volatile("fence.proxy.async.shared::cta;" ::: "memory");
                const int od = 2 * (d0 + p);
                float* g0 = dst + ((size_t)od * DOUT + 2 * h0) * DOUT;
                float* g1 = g0 + (size_t)DOUT * DOUT;
                asm volatile(
                    "cp.async.bulk.global.shared::cta.bulk_group [%0], [%1], %2;"
                    :: "l"(g0), "r"(sm32(&stg[buf][0][0][0])),
                       "r"(2 * TH * DOUT * 4) : "memory");
                asm volatile(
                    "cp.async.bulk.global.shared::cta.bulk_group [%0], [%1], %2;"
                    :: "l"(g1), "r"(sm32(&stg[buf][1][0][0])),
                       "r"(2 * TH * DOUT * 4) : "memory");
                asm volatile("cp.async.bulk.commit_group;" ::: "memory");
            }
        }
    }

    // drain all outstanding bulk stores before exit
    if (tid == 0)
        asm volatile("cp.async.bulk.wait_group 0;" ::: "memory");
}

extern "C" void kernel_launch(void* const* d_in, const int* in_sizes, int n_in,
                              void* d_out, int out_size)
{
    const float* x = (const float*)d_in[0];
    float* y = (float*)d_out;
    dim3 block(24, 8, 1);                        // 192 threads
    dim3 grid(DIN / TH, DIN / TD, 128);          // 6 x 8 x (N*C) = 6144 blocks
    upsample3d_kernel<<<grid, block>>>(x, y);
}